// round 11
// baseline (speedup 1.0000x reference)
#include <cuda_runtime.h>
#include <cuda_bf16.h>
#include <mma.h>
#include <math.h>
#include <stdint.h>

using namespace nvcuda;

// ---------------- scratch (allocation-free: __device__ globals) ----------------
__device__ float g_bufA[660000];
__device__ float g_bufB[660000];
__device__ float g_h[100 * 512];
__device__ float g_q[100 * 512];
__device__ float g_k[100 * 512];
__device__ float g_v[100 * 1024];
__device__ float g_part[819200];
__device__ __align__(16) __nv_bfloat16 g_wh[44564480];   // split-bf16 weight pool (hi)
__device__ __align__(16) __nv_bfloat16 g_wl[44564480];   // (lo)
__device__ __align__(16) __nv_bfloat16 g_acth[204800];   // activation bf16 hi [100*2048 max]
__device__ __align__(16) __nv_bfloat16 g_actl[204800];
__device__ int g_count = 0;
__device__ volatile int g_sense = 0;

#define NCTA 128
#define NTHR 256
#define DSM_BYTES 168960
#define HU_BYTES 40960

// weight pool offsets (elements)
#define OFF_Q  0ull
#define OFF_K  3145728ull
#define OFF_V  6291456ull
#define OFF_O  12582912ull
#define OFF_1  18874368ull
#define OFF_2  31457280ull
#define OFF_C10 44040192ull
#define W_TOTAL 44564480ull

// ---------------- global barrier ----------------
__device__ __forceinline__ void gbar(int* lsense) {
    __syncthreads();
    if (threadIdx.x == 0) {
        __threadfence();
        *lsense ^= 1;
        if (atomicAdd(&g_count, 1) == NCTA - 1) {
            g_count = 0;
            __threadfence();
            g_sense = *lsense;
        } else {
            while (g_sense != *lsense) __nanosleep(32);
        }
        __threadfence();
    }
    __syncthreads();
}

// ---------------- weight split-conversion (once per launch) ----------------
__global__ __launch_bounds__(256) void wconv_kernel(
    const float* __restrict__ Wq, const float* __restrict__ Wk,
    const float* __restrict__ Wv, const float* __restrict__ Wo,
    const float* __restrict__ W1, const float* __restrict__ W2,
    const float* __restrict__ cw10)
{
    for (size_t i = ((size_t)blockIdx.x * 256 + threadIdx.x) * 4;
         i < W_TOTAL; i += (size_t)gridDim.x * 1024) {
        const float* src;
        size_t off;
        if (i < OFF_K)        { src = Wq;   off = i; }
        else if (i < OFF_V)   { src = Wk;   off = i - OFF_K; }
        else if (i < OFF_O)   { src = Wv;   off = i - OFF_V; }
        else if (i < OFF_1)   { src = Wo;   off = i - OFF_O; }
        else if (i < OFF_2)   { src = W1;   off = i - OFF_1; }
        else if (i < OFF_C10) { src = W2;   off = i - OFF_2; }
        else                  { src = cw10; off = i - OFF_C10; }
        const float4 v = *(const float4*)(src + off);
        __nv_bfloat16 h[4], l[4];
        const float vv[4] = {v.x, v.y, v.z, v.w};
#pragma unroll
        for (int j = 0; j < 4; j++) {
            h[j] = __float2bfloat16_rn(vv[j]);
            l[j] = __float2bfloat16_rn(vv[j] - __bfloat162float(h[j]));
        }
        *(uint2*)(g_wh + i) = *(uint2*)h;
        *(uint2*)(g_wl + i) = *(uint2*)l;
    }
}

// ================= HMMA core: all-bf16 staging (pure copies) =================
struct __align__(32) HSM {
    __nv_bfloat16 Ah[64 * 80];
    __nv_bfloat16 Al[64 * 80];
    __nv_bfloat16 Bh[64 * 80];
    __nv_bfloat16 Bl[64 * 80];
};
union __align__(32) HU {
    HSM s;
    float C[64 * 64];
};

template <bool NKW>
__device__ __forceinline__ void hmma_core_bf(
    HU& u, int t,
    const __nv_bfloat16* __restrict__ Ah, const __nv_bfloat16* __restrict__ Al, int K,
    const __nv_bfloat16* __restrict__ Bh, const __nv_bfloat16* __restrict__ Bl, int ldB,
    int nk, int mvalid)
{
    const int wid = t >> 5;
    const int wm = wid >> 1, wn = wid & 1;

    wmma::fragment<wmma::accumulator, 16, 16, 16, float> c[2][2];
#pragma unroll
    for (int i = 0; i < 2; i++)
#pragma unroll
        for (int j = 0; j < 2; j++) wmma::fill_fragment(c[i][j], 0.0f);

    for (int kt = 0; kt < nk; kt++) {
        const int k0 = kt << 6;
#pragma unroll
        for (int i = 0; i < 4; i++) {
            const int e = t + (i << 7);
            const int m = e >> 3, c8 = (e & 7) << 3;
            uint4 vh = make_uint4(0, 0, 0, 0), vl = make_uint4(0, 0, 0, 0);
            if (m < mvalid) {
                vh = *(const uint4*)(Ah + (size_t)m * K + k0 + c8);
                vl = *(const uint4*)(Al + (size_t)m * K + k0 + c8);
            }
            *(uint4*)&u.s.Ah[m * 80 + c8] = vh;
            *(uint4*)&u.s.Al[m * 80 + c8] = vl;
        }
#pragma unroll
        for (int i = 0; i < 4; i++) {
            const int e = t + (i << 7);
            if (!NKW) {
                const int k = e >> 3, n8 = (e & 7) << 3;
                const uint4 vh = *(const uint4*)(Bh + (size_t)(k0 + k) * ldB + n8);
                const uint4 vl = *(const uint4*)(Bl + (size_t)(k0 + k) * ldB + n8);
                *(uint4*)&u.s.Bh[k * 80 + n8] = vh;
                *(uint4*)&u.s.Bl[k * 80 + n8] = vl;
            } else {
                const int nn = e >> 3, k8 = (e & 7) << 3;
                const uint4 vh = *(const uint4*)(Bh + (size_t)nn * ldB + k0 + k8);
                const uint4 vl = *(const uint4*)(Bl + (size_t)nn * ldB + k0 + k8);
                const __nv_bfloat16* ph = (const __nv_bfloat16*)&vh;
                const __nv_bfloat16* pl = (const __nv_bfloat16*)&vl;
#pragma unroll
                for (int j = 0; j < 8; j++) {
                    u.s.Bh[(k8 + j) * 80 + nn] = ph[j];
                    u.s.Bl[(k8 + j) * 80 + nn] = pl[j];
                }
            }
        }
        __syncthreads();
#pragma unroll
        for (int kk = 0; kk < 4; kk++) {
            wmma::fragment<wmma::matrix_a, 16, 16, 16, __nv_bfloat16, wmma::row_major> ah[2], al[2];
            wmma::fragment<wmma::matrix_b, 16, 16, 16, __nv_bfloat16, wmma::row_major> bh[2], bl[2];
#pragma unroll
            for (int i = 0; i < 2; i++) {
                wmma::load_matrix_sync(ah[i], &u.s.Ah[(wm * 32 + i * 16) * 80 + kk * 16], 80);
                wmma::load_matrix_sync(al[i], &u.s.Al[(wm * 32 + i * 16) * 80 + kk * 16], 80);
            }
#pragma unroll
            for (int j = 0; j < 2; j++) {
                wmma::load_matrix_sync(bh[j], &u.s.Bh[(kk * 16) * 80 + wn * 32 + j * 16], 80);
                wmma::load_matrix_sync(bl[j], &u.s.Bl[(kk * 16) * 80 + wn * 32 + j * 16], 80);
            }
#pragma unroll
            for (int i = 0; i < 2; i++)
#pragma unroll
                for (int j = 0; j < 2; j++) {
                    wmma::mma_sync(c[i][j], ah[i], bh[j], c[i][j]);
                    wmma::mma_sync(c[i][j], ah[i], bl[j], c[i][j]);
                    wmma::mma_sync(c[i][j], al[i], bh[j], c[i][j]);
                }
        }
        __syncthreads();
    }
#pragma unroll
    for (int i = 0; i < 2; i++)
#pragma unroll
        for (int j = 0; j < 2; j++)
            wmma::store_matrix_sync(&u.C[(wm * 32 + i * 16) * 64 + wn * 32 + j * 16],
                                    c[i][j], 64, wmma::mem_row_major);
    __syncthreads();
}

template <bool NKW>
__device__ __forceinline__ void gemm_unit_bf(
    HU& u, int t, const __nv_bfloat16* Ah, const __nv_bfloat16* Al, int K,
    const __nv_bfloat16* Bh, const __nv_bfloat16* Bl, int ldB, int nk, int m0,
    float* P, int N)
{
    hmma_core_bf<NKW>(u, t, Ah, Al, K, Bh, Bl, ldB, nk, 100 - m0);
#pragma unroll
    for (int i = 0; i < 8; i++) {
        const int e = t + (i << 7);
        const int m = e >> 4, n4 = (e & 15) << 2;
        if (m0 + m < 100)
            *(float4*)&P[(size_t)m * N + n4] = *(float4*)&u.C[m * 64 + n4];
    }
}

// combine: out = sum_s part[s]; mode 0 plain, 1 +locemb, 2 qkv-dispatch
// emit != 0 -> also write bf16 hi/lo of result to g_acth/g_actl at [row*N+n]
__device__ __forceinline__ void combine_phase(
    const float* part, int S, int N, const float* bias,
    const float* resid, float* out, int relu, int mode, int emit)
{
    const int total4 = 100 * N / 4;
    for (int idx = blockIdx.x * NTHR + threadIdx.x; idx < total4; idx += NCTA * NTHR) {
        const int base = idx * 4;
        const int n = base % N;
        const int row = base / N;
        float4 v = *(const float4*)&part[base];
        for (int s = 1; s < S; s++) {
            const float4 p = *(const float4*)&part[(size_t)s * 100 * N + base];
            v.x += p.x; v.y += p.y; v.z += p.z; v.w += p.w;
        }
        if (mode == 2) {
            if (n < 512) {
                v.x *= 0.1f; v.y *= 0.1f; v.z *= 0.1f; v.w *= 0.1f;
                *(float4*)&g_q[row * 512 + n] = v;
            } else if (n < 1024) {
                *(float4*)&g_k[row * 512 + n - 512] = v;
            } else {
                *(float4*)&g_v[row * 1024 + n - 1024] = v;
            }
            continue;
        }
        if (bias) {
            const float4 b = *(const float4*)&bias[n];
            v.x += b.x; v.y += b.y; v.z += b.z; v.w += b.w;
        }
        if (relu) {
            v.x = fmaxf(v.x, 0.f); v.y = fmaxf(v.y, 0.f);
            v.z = fmaxf(v.z, 0.f); v.w = fmaxf(v.w, 0.f);
        }
        if (resid) {
            const float4 r = *(const float4*)&resid[base];
            v.x += r.x; v.y += r.y; v.z += r.z; v.w += r.w;
        }
        if (mode == 1) {
            const float pos = 20.0f * (float)(row / 10);
            float* vp = &v.x;
#pragma unroll
            for (int j = 0; j < 4; j++) {
                const int d = n + j;
                const int k = d & 255;
                const float ang = pos * exp2f(-0.10381025296523009f * (float)k);
                vp[j] += (d < 256) ? sinf(ang) : cosf(ang);
            }
        }
        if (out) *(float4*)&out[base] = v;
        if (emit) {
            const float vv[4] = {v.x, v.y, v.z, v.w};
            __nv_bfloat16 h[4], l[4];
#pragma unroll
            for (int j = 0; j < 4; j++) {
                h[j] = __float2bfloat16_rn(vv[j]);
                l[j] = __float2bfloat16_rn(vv[j] - __bfloat162float(h[j]));
            }
            *(uint2*)(g_acth + base) = *(uint2*)h;
            *(uint2*)(g_actl + base) = *(uint2*)l;
        }
    }
}

// ---------------- megakernel ----------------
__global__ __launch_bounds__(NTHR, 1) void mega_kernel(
    const float* __restrict__ cb10,
    const float* __restrict__ b1, const float* __restrict__ b2,
    float* __restrict__ d_out)
{
    extern __shared__ char dsm[];
    int lsense = 0;
    const int cta = blockIdx.x;
    const int tid = threadIdx.x;
    const int half = tid >> 7;
    const int lt = tid & 127;
    HU& u = *(HU*)(dsm + half * HU_BYTES);
    const int unit = cta * 2 + half;

    // ---- conv10: A[100,1024](act bf16) @ cw10^T, S=16, nk=1 ----
    {
        const int s = unit & 15, nt = (unit >> 4) & 7, mt = unit >> 7;
        const int m0 = mt * 64, n0 = nt * 64;
        const size_t bo = OFF_C10 + (size_t)n0 * 1024 + s * 64;
        gemm_unit_bf<true>(u, lt, g_acth + (size_t)m0 * 1024 + s * 64,
                           g_actl + (size_t)m0 * 1024 + s * 64, 1024,
                           g_wh + bo, g_wl + bo, 1024, 1, m0,
                           g_part + ((size_t)s * 100 + m0) * 512 + n0, 512);
    }
    gbar(&lsense);                                               // bar 1
    combine_phase(g_part, 16, 512, cb10, nullptr, g_h, 0, 1, 512);
    gbar(&lsense);                                               // bar 2

    for (int n = 0; n < 12; n++) {
        const float* Lb1 = b1 + (size_t)n * 2048;
        const float* Lb2 = b2 + (size_t)n * 512;

        // ---- QKV concat [100,2048], S=4, nk=2 ----
        {
            const int s = unit & 3, nt = (unit >> 2) & 31, mt = unit >> 7;
            const int m0 = mt * 64;
            const int col0 = nt * 64;
            size_t bo;
            int ldB2;
            if (col0 < 512) {
                bo = OFF_Q + (size_t)n * 262144 + (size_t)(col0 >> 7) * 65536
                     + s * 16384 + (col0 & 127);
                ldB2 = 128;
            } else if (col0 < 1024) {
                const int c = col0 - 512;
                bo = OFF_K + (size_t)n * 262144 + (size_t)(c >> 7) * 65536
                     + s * 16384 + (c & 127);
                ldB2 = 128;
            } else {
                const int c = col0 - 1024;
                bo = OFF_V + (size_t)n * 524288 + (size_t)(c >> 8) * 131072
                     + s * 32768 + (c & 255);
                ldB2 = 256;
            }
            gemm_unit_bf<false>(u, lt, g_acth + (size_t)m0 * 512 + s * 128,
                                g_actl + (size_t)m0 * 512 + s * 128, 512,
                                g_wh + bo, g_wl + bo, ldB2, 2, m0,
                                g_part + ((size_t)s * 100 + m0) * 2048 + col0, 2048);
        }
        gbar(&lsense);                                           // bar 3
        combine_phase(g_part, 4, 2048, nullptr, nullptr, nullptr, 0, 2, 0);
        gbar(&lsense);                                           // bar 4

        // ---- attention: 40 whole-CTA units; writes ocat bf16 ----
        if (cta < 40) {
            float* ks = (float*)dsm;
            float* vs = ks + 13200;
            float* qs = vs + 25600;
            float* prow = qs + 1320;
            const int h4 = cta / 10, rg = cta % 10;
            const int w = tid >> 5, lane = tid & 31;

            for (int idx = tid; idx < 100 * 128; idx += NTHR) {
                const int m = idx >> 7, d = idx & 127;
                ks[m * 132 + d] = g_k[m * 512 + h4 * 128 + d];
            }
            for (int idx = tid; idx < 100 * 256; idx += NTHR) {
                const int m = idx >> 8, dv = idx & 255;
                vs[idx] = g_v[m * 1024 + h4 * 256 + dv];
            }
            for (int idx = tid; idx < 10 * 128; idx += NTHR) {
                const int r = idx >> 7, d = idx & 127;
                qs[r * 132 + d] = g_q[(rg * 10 + r) * 512 + h4 * 128 + d];
            }
            __syncthreads();

#pragma unroll
            for (int rr = 0; rr < 2; rr++) {
                const int r = w + rr * 8;
                if (r >= 10) break;
                const float4* q4 = (const float4*)(qs + r * 132);
                float sc[4];
#pragma unroll
                for (int j = 0; j < 4; j++) {
                    const int m = lane + 32 * j;
                    if (m < 100) {
                        const float4* k4 = (const float4*)(ks + m * 132);
                        float acc = 0.0f;
#pragma unroll
                        for (int dd = 0; dd < 32; dd++) {
                            const float4 kv = k4[dd];
                            const float4 qv = q4[dd];
                            acc += qv.x * kv.x + qv.y * kv.y + qv.z * kv.z + qv.w * kv.w;
                        }
                        sc[j] = acc;
                    } else sc[j] = -1e30f;
                }
                float mx = fmaxf(fmaxf(sc[0], sc[1]), fmaxf(sc[2], sc[3]));
#pragma unroll
                for (int o = 16; o; o >>= 1) mx = fmaxf(mx, __shfl_xor_sync(0xffffffffu, mx, o));
                float e[4], sum = 0.0f;
#pragma unroll
                for (int j = 0; j < 4; j++) { e[j] = __expf(sc[j] - mx); sum += e[j]; }
#pragma unroll
                for (int o = 16; o; o >>= 1) sum += __shfl_xor_sync(0xffffffffu, sum, o);
                const float inv = 1.0f / sum;
#pragma unroll
                for (int j = 0; j < 4; j++) {
                    const int m = lane + 32 * j;
                    if (m < 100) prow[r * 104 + m] = e[j] * inv;
                }
                __syncwarp();

                float acc[8] = {};
                const float* pr = prow + r * 104;
#pragma unroll 4
                for (int m = 0; m < 100; m++) {
                    const float p = pr[m];
                    const float* vr = vs + m * 256 + lane;
#pragma unroll
                    for (int j = 0; j < 8; j++) acc[j] += p * vr[32 * j];
                }
                const int row = rg * 10 + r;
                const size_t ob = (size_t)row * 1024 + h4 * 256 + lane;
#pragma unroll
                for (int j = 0; j < 8; j++) {
                    const float x = acc[j];
                    const __nv_bfloat16 hb = __float2bfloat16_rn(x);
                    g_acth[ob + 32 * j] = hb;
                    g_actl[ob + 32 * j] = __float2bfloat16_rn(x - __bfloat162float(hb));
                }
            }
        }
        gbar(&lsense);                                           // bar 5

        // ---- Wo: A=ocat bf16 [100,1024], S=16, nk=1 ----
        {
            const int s = unit & 15, nt = (unit >> 4) & 7, mt = unit >> 7;
            const int m0 = mt * 64, n0 = nt * 64;
            const size_t bo = OFF_O + (size_t)n * 524288 + (size_t)(s * 64) * 512 + n0;
            gemm_unit_bf<false>(u, lt, g_acth + (size_t)m0 * 1024 + s * 64,
                                g_actl + (size_t)m0 * 1024 + s * 64, 1024,
                                g_wh + bo, g_wl + bo, 512, 1, m0,
                                g_part + ((size_t)s * 100 + m0) * 512 + n0, 512);
        }
        gbar(&lsense);                                           // bar 6
        combine_phase(g_part, 16, 512, nullptr, g_h, g_h, 0, 0, 512);
        gbar(&lsense);                                           // bar 7

        // ---- FFN1: A=h bf16 [100,512], S=4, nk=2 ----
        {
            const int s = unit & 3, nt = (unit >> 2) & 31, mt = unit >> 7;
            const int m0 = mt * 64, n0 = nt * 64;
            const size_t bo = OFF_1 + (size_t)n * 1048576 + (size_t)(s * 128) * 2048 + n0;
            gemm_unit_bf<false>(u, lt, g_acth + (size_t)m0 * 512 + s * 128,
                                g_actl + (size_t)m0 * 512 + s * 128, 512,
                                g_wh + bo, g_wl + bo, 2048, 2, m0,
                                g_part + ((size_t)s * 100 + m0) * 2048 + n0, 2048);
        }
        gbar(&lsense);                                           // bar 8
        combine_phase(g_part, 4, 2048, Lb1, nullptr, nullptr, 1, 0, 2048);
        gbar(&lsense);                                           // bar 9

        // ---- FFN2: A=ffn bf16 [100,2048], S=16, nk=2 ----
        {
            const int s = unit & 15, nt = (unit >> 4) & 7, mt = unit >> 7;
            const int m0 = mt * 64, n0 = nt * 64;
            const size_t bo = OFF_2 + (size_t)n * 1048576 + (size_t)(s * 128) * 512 + n0;
            gemm_unit_bf<false>(u, lt, g_acth + (size_t)m0 * 2048 + s * 128,
                                g_actl + (size_t)m0 * 2048 + s * 128, 2048,
                                g_wh + bo, g_wl + bo, 512, 2, m0,
                                g_part + ((size_t)s * 100 + m0) * 512 + n0, 512);
        }
        gbar(&lsense);                                           // bar 10
        combine_phase(g_part, 16, 512, Lb2, g_h, (n == 11) ? d_out : g_h, 0, 0,
                      (n == 11) ? 0 : 512);
        gbar(&lsense);                                           // bar 11
    }
}

// ---------------- conv layers 1-9 ----------------
template <int CIN, int HIN, int COUT, int KS, int COG, bool RELU, bool FIRST, bool EMIT>
__global__ __launch_bounds__(128) void conv_kernel(
    const float* __restrict__ in, const float* __restrict__ W,
    const float* __restrict__ bias, float* __restrict__ out)
{
    constexpr int HOUT = HIN - KS + 1;
    constexpr int WOUT = HOUT;
    constexpr int INSZ = CIN * HIN * HIN;
    constexpr int HW = HOUT * WOUT;
    __shared__ float sin_[INSZ];

    const int p = blockIdx.x;
    const int co0 = blockIdx.y * COG;

    if (FIRST) {
        const int ib = p / 10, jb = p % 10;
        for (int idx = threadIdx.x; idx < INSZ; idx += blockDim.x) {
            const int c = idx / (HIN * HIN);
            const int rem = idx % (HIN * HIN);
            const int r = rem / HIN, cc = rem % HIN;
            sin_[idx] = in[c * 40000 + (20 * jb + r) * 200 + (20 * ib + cc)];
        }
    } else {
        const float* src = in + p * INSZ;
        for (int idx = threadIdx.x; idx < INSZ; idx += blockDim.x)
            sin_[idx] = src[idx];
    }
    __syncthreads();

    for (int pair = threadIdx.x; pair < COG * HOUT; pair += blockDim.x) {
        const int co = co0 + pair / HOUT;
        const int py = pair % HOUT;
        float acc[WOUT];
        const float bv = bias[co];
#pragma unroll
        for (int px = 0; px < WOUT; px++) acc[px] = bv;
        const float* wbase = W + co * CIN * KS * KS;
        for (int ci = 0; ci < CIN; ci++) {
#pragma unroll
            for (int ky = 0; ky < KS; ky++) {
                const float* irow = sin_ + ci * HIN * HIN + (py + ky) * HIN;
                float w[KS];
#pragma unroll
                for (int kx = 0; kx < KS; kx++)
                    w[kx] = wbase[ci * KS * KS + ky * KS + kx];
#pragma unroll
                for (int px = 0; px < WOUT; px++) {
#pragma unroll
                    for (int kx = 0; kx < KS; kx++)
                        acc[px] += w[kx] * irow[px + kx];
                }
            }
        }
        const size_t obase = (size_t)p * COUT * HW + co * HW + py * WOUT;
#pragma unroll
        for (int px = 0; px < WOUT; px++) {
            float v = acc[px];
            if (RELU) v = fmaxf(v, 0.0f);
            if (EMIT) {
                const __nv_bfloat16 hb = __float2bfloat16_rn(v);
                g_acth[obase + px] = hb;
                g_actl[obase + px] = __float2bfloat16_rn(v - __bfloat162float(hb));
            } else {
                out[obase + px] = v;
            }
        }
    }
}

// ---------------- launch ----------------
extern "C" void kernel_launch(void* const* d_in, const int* in_sizes, int n_in,
                              void* d_out, int out_size)
{
    (void)in_sizes; (void)n_in; (void)out_size;
    const float* x = (const float*)d_in[0];
    const float* cw[10];
    const float* cb[10];
    for (int i = 0; i < 10; i++) {
        cw[i] = (const float*)d_in[1 + 2 * i];
        cb[i] = (const float*)d_in[2 + 2 * i];
    }
    const float* Wq = (const float*)d_in[21];
    const float* Wk = (const float*)d_in[22];
    const float* Wv = (const float*)d_in[23];
    const float* Wo = (const float*)d_in[24];
    const float* W1 = (const float*)d_in[25];
    const float* b1 = (const float*)d_in[26];
    const float* W2 = (const float*)d_in[27];
    const float* b2 = (const float*)d_in[28];

    float *bufA, *bufB;
    cudaGetSymbolAddress((void**)&bufA, g_bufA);
    cudaGetSymbolAddress((void**)&bufB, g_bufB);

    cudaFuncSetAttribute(mega_kernel, cudaFuncAttributeMaxDynamicSharedMemorySize, DSM_BYTES);

    // split-convert all weights to bf16 hi/lo pool (overlaps conv stack on GPU)
    wconv_kernel<<<1024, 256>>>(Wq, Wk, Wv, Wo, W1, W2, cw[9]);

    // Conv stack (RELU_AFTER = F T F T T T T T T F); conv9 emits bf16 activations
    conv_kernel<3, 20, 8, 3, 8, false, true, false><<<dim3(100, 1), 128>>>(x, cw[0], cb[0], bufA);
    conv_kernel<8, 18, 16, 3, 8, true, false, false><<<dim3(100, 2), 128>>>(bufA, cw[1], cb[1], bufB);
    conv_kernel<16, 16, 32, 3, 8, false, false, false><<<dim3(100, 4), 128>>>(bufB, cw[2], cb[2], bufA);
    conv_kernel<32, 14, 32, 3, 8, true, false, false><<<dim3(100, 4), 128>>>(bufA, cw[3], cb[3], bufB);
    conv_kernel<32, 12, 64, 3, 16, true, false, false><<<dim3(100, 4), 128>>>(bufB, cw[4], cb[4], bufA);
    conv_kernel<64, 10, 64, 3, 16, true, false, false><<<dim3(100, 4), 128>>>(bufA, cw[5], cb[5], bufB);
    conv_kernel<64, 8, 128, 3, 32, true, false, false><<<dim3(100, 4), 128>>>(bufB, cw[6], cb[6], bufA);
    conv_kernel<128, 6, 128, 3, 32, true, false, false><<<dim3(100, 4), 128>>>(bufA, cw[7], cb[7], bufB);
    conv_kernel<128, 4, 256, 3, 64, true, false, true><<<dim3(100, 4), 128>>>(bufB, cw[8], cb[8], bufA);

    // conv10 + locadd + 12 encoder layers in one persistent kernel
    mega_kernel<<<NCTA, NTHR, DSM_BYTES>>>(cb[9], b1, b2, (float*)d_out);
}